// round 7
// baseline (speedup 1.0000x reference)
#include <cuda_runtime.h>
#include <cuda.h>
#include <cuda_fp16.h>
#include <cstdint>

// Problem dims
#define NM 64
#define NK 4096
#define NW 14336
#define NTILE 128           // N columns per CTA
#define KC 128              // K per chunk
#define NITER 32            // NK/KC
#define NBLK 112            // NW/NTILE
#define THREADS 512

// SMEM layout: 2 buffers x (W int32 64KB + X fp16 16KB), then mbarriers
#define BUFB   81920
#define SM_XOFF 65536
#define SM_MB  163840       // two 8-byte mbarriers
#define SMEM_TOTAL 163904

// Global scratch: pre-swizzled fp16 x image (32 chunks x 16KB) + rowsum
__device__ __align__(16) unsigned char g_ximg[NITER * 16384];
__device__ float g_rowsum[NM];

// ---------------- helpers ----------------
__device__ __forceinline__ uint32_t smem_u32(const void* p) {
    uint32_t a;
    asm("{ .reg .u64 t; cvta.to.shared.u64 t, %1; cvt.u32.u64 %0, t; }" : "=r"(a) : "l"(p));
    return a;
}

#define MBARRIER_INIT(addr, cnt) \
    asm volatile("mbarrier.init.shared.b64 [%0], %1;" :: "r"((uint32_t)(addr)), "r"((uint32_t)(cnt)) : "memory")

#define MBARRIER_EXPECT_TX(addr, bytes) \
    asm volatile("mbarrier.arrive.expect_tx.shared.b64 _, [%0], %1;" \
        :: "r"((uint32_t)(addr)), "r"((uint32_t)(bytes)) : "memory")

#define MBARRIER_WAIT_PARITY(mbar, par) do {                                        \
    uint32_t _m = (uint32_t)(mbar); uint32_t _p = (uint32_t)(par); uint32_t _d;     \
    asm volatile("{ .reg .pred p;\n"                                                \
        "mbarrier.try_wait.parity.acquire.cta.shared::cta.b64 p, [%1], %2;\n"       \
        "selp.b32 %0, 1, 0, p; }"                                                   \
        : "=r"(_d) : "r"(_m), "r"(_p) : "memory");                                  \
    if (!_d) {                                                                      \
        asm volatile("{ .reg .pred P1;\n"                                           \
            "WL_%=:\n"                                                              \
            "mbarrier.try_wait.parity.acquire.cta.shared::cta.b64 P1, [%0], %1, 0x989680;\n" \
            "@P1 bra.uni WD_%=;\n"                                                  \
            "bra.uni WL_%=;\n"                                                      \
            "WD_%=: }" :: "r"(_m), "r"(_p) : "memory");                             \
    }                                                                               \
} while (0)

__device__ __forceinline__ void tma_2d(uint32_t dst, const void* map, int cx, int cy, uint32_t mbar) {
    asm volatile(
        "cp.async.bulk.tensor.2d.shared::cluster.global.tile.mbarrier::complete_tx::bytes "
        "[%0], [%1, {%2, %3}], [%4];"
        :: "r"(dst), "l"(map), "r"(cx), "r"(cy), "r"(mbar) : "memory");
}
__device__ __forceinline__ void bulk_g2s(uint32_t dst, const void* src, uint32_t bytes, uint32_t mbar) {
    asm volatile(
        "cp.async.bulk.shared::cluster.global.mbarrier::complete_tx::bytes "
        "[%0], [%1], %2, [%3];"
        :: "r"(dst), "l"(src), "r"(bytes), "r"(mbar) : "memory");
}
__device__ __forceinline__ void ldmatrix_x4(uint32_t* r, uint32_t addr) {
    asm volatile("ldmatrix.sync.aligned.m8n8.x4.shared.b16 {%0,%1,%2,%3}, [%4];"
        : "=r"(r[0]), "=r"(r[1]), "=r"(r[2]), "=r"(r[3]) : "r"(addr));
}
__device__ __forceinline__ uint32_t lds32(uint32_t addr) {
    uint32_t v;
    asm volatile("ld.shared.b32 %0, [%1];" : "=r"(v) : "r"(addr));
    return v;
}
__device__ __forceinline__ uint32_t pack_f16x2(int lo, int hi) {
    float fl, fh; uint32_t d;
    asm("cvt.rn.f32.s32 %0, %1;" : "=f"(fl) : "r"(lo));
    asm("cvt.rn.f32.s32 %0, %1;" : "=f"(fh) : "r"(hi));
    asm("cvt.rn.f16x2.f32 %0, %1, %2;" : "=r"(d) : "f"(fh), "f"(fl));
    return d;
}
__device__ __forceinline__ void mma16816(float* d, const uint32_t* a, const uint32_t* b) {
    asm volatile(
        "mma.sync.aligned.m16n8k16.row.col.f32.f16.f16.f32 "
        "{%0,%1,%2,%3}, {%4,%5,%6,%7}, {%8,%9}, {%0,%1,%2,%3};"
        : "+f"(d[0]), "+f"(d[1]), "+f"(d[2]), "+f"(d[3])
        : "r"(a[0]), "r"(a[1]), "r"(a[2]), "r"(a[3]), "r"(b[0]), "r"(b[1]));
}

// ---------------- prep kernels ----------------
// x fp32 -> fp16 image, swizzled for conflict-free ldmatrix:
// chunk c, addr = c*16384 + m*256 + ((kl*2) ^ ((m&7)<<4))
__global__ void prep_x(const float* __restrict__ x) {
    int idx = blockIdx.x * 256 + threadIdx.x;   // 32768 total
    int m = idx >> 9;                           // 0..63
    int k = (idx & 511) << 3;                   // 0..4088, 8-aligned
    const float4* xp = reinterpret_cast<const float4*>(x + m * NK + k);
    float4 a = xp[0], b = xp[1];
    float v[8] = {a.x, a.y, a.z, a.w, b.x, b.y, b.z, b.w};
    __align__(16) __half h[8];
#pragma unroll
    for (int i = 0; i < 8; i++) h[i] = __float2half_rn(v[i]);
    int c = k >> 7;
    int kl = k & 127;
    uint32_t off = (uint32_t)c * 16384u + (uint32_t)m * 256u + (((uint32_t)kl * 2u) ^ (((uint32_t)m & 7u) << 4));
    *reinterpret_cast<uint4*>(g_ximg + off) = *reinterpret_cast<uint4*>(h);
}

__global__ void prep_rowsum(const float* __restrict__ x) {
    __shared__ float red[4];
    int m = blockIdx.x;
    float s = 0.f;
    for (int k = threadIdx.x; k < NK; k += 128) s += x[m * NK + k];
#pragma unroll
    for (int o = 16; o; o >>= 1) s += __shfl_xor_sync(0xffffffffu, s, o);
    if ((threadIdx.x & 31) == 0) red[threadIdx.x >> 5] = s;
    __syncthreads();
    if (threadIdx.x == 0) g_rowsum[m] = red[0] + red[1] + red[2] + red[3];
}

// ---------------- main kernel ----------------
__global__ __launch_bounds__(THREADS, 1) void wqmm_main(
    const __grid_constant__ CUtensorMap tmw,
    const float* __restrict__ scale,
    const float* __restrict__ offs,
    const float* __restrict__ bias,
    float* __restrict__ out)
{
    extern __shared__ char smem[];
    const uint32_t sb = smem_u32(smem);
    const int tid = threadIdx.x;
    const int wid = tid >> 5;
    const int lane = tid & 31;
    const int g = lane >> 2;     // groupID
    const int tg = lane & 3;     // thread-in-group
    const int n0 = blockIdx.x * NTILE;

    const int mw = wid >> 3;     // 0..1 : m-half (32 rows)
    const int nw = wid & 7;      // 0..7 : n16 slice

    // mbarrier init
    if (tid == 0) {
        MBARRIER_INIT(sb + SM_MB + 0, 1);
        MBARRIER_INIT(sb + SM_MB + 8, 1);
        asm volatile("fence.mbarrier_init.release.cluster;" ::: "memory");
    }
    __syncthreads();

    // producer: issue chunk c into buffer b
    auto issue = [&](int c, int b) {
        uint32_t mb = sb + SM_MB + (uint32_t)b * 8;
        uint32_t wdst = sb + (uint32_t)b * BUFB;
        MBARRIER_EXPECT_TX(mb, 81920);
#pragma unroll
        for (int bx = 0; bx < 4; bx++)
            tma_2d(wdst + (uint32_t)bx * 16384, &tmw, n0 + bx * 32, c * KC, mb);
        bulk_g2s(wdst + SM_XOFF, g_ximg + (size_t)c * 16384, 16384, mb);
    };

    if (tid == 0) { issue(0, 0); issue(1, 1); }

    // per-thread constant addressing
    // A (x) ldmatrix: row = mw*32 + (lane&8) + (lane&7); col byte = ks*32 + ((lane>>4)&1)*16
    const uint32_t rbase = (uint32_t)(mw * 32 + (lane & 8) + (lane & 7));
    const uint32_t aswx = ((uint32_t)(lane & 7)) << 4;
    const uint32_t akq = ((uint32_t)((lane >> 4) & 1)) * 16;
    const uint32_t aoff = rbase * 256;

    // B (w) LDS: box = nw>>1; nl = (nw&1)*16 + nt*8 + g
    const uint32_t boxoff = ((uint32_t)(nw >> 1)) * 16384u;
    uint32_t c0[2], c1[2];
#pragma unroll
    for (int nt = 0; nt < 2; nt++) {
        uint32_t nl = (uint32_t)((nw & 1) * 16 + nt * 8 + g);
        c0[nt] = (nl * 4u) ^ (((uint32_t)(tg * 2)) << 4);
        c1[nt] = (nl * 4u) ^ (((uint32_t)(tg * 2 + 1)) << 4);
    }
    const uint32_t tgrow = (uint32_t)(tg * 2) * 128u;

    float acc[2][2][4];
#pragma unroll
    for (int i = 0; i < 2; i++)
#pragma unroll
        for (int j = 0; j < 2; j++)
#pragma unroll
            for (int q = 0; q < 4; q++) acc[i][j][q] = 0.f;

    for (int it = 0; it < NITER; ++it) {
        const int b = it & 1;
        MBARRIER_WAIT_PARITY(sb + SM_MB + b * 8, (it >> 1) & 1);

        const uint32_t wb = sb + (uint32_t)b * BUFB + boxoff;
        const uint32_t xb = sb + (uint32_t)b * BUFB + SM_XOFF;

#pragma unroll
        for (int ks = 0; ks < 8; ks++) {
            // A fragments (two m16 tiles)
            uint32_t a0[4], a1[4];
            uint32_t acol = ((uint32_t)(ks * 32) + akq) ^ aswx;
            uint32_t xaddr = xb + aoff + acol;
            ldmatrix_x4(a0, xaddr);
            ldmatrix_x4(a1, xaddr + 4096);

            const uint32_t kb = wb + (uint32_t)ks * 2048u + tgrow;
#pragma unroll
            for (int nt = 0; nt < 2; nt++) {
                int w00 = (int)lds32(kb + c0[nt]);
                int w01 = (int)lds32(kb + 128 + c1[nt]);
                int w08 = (int)lds32(kb + 1024 + c0[nt]);
                int w09 = (int)lds32(kb + 1152 + c1[nt]);
                uint32_t bfr[2];
                bfr[0] = pack_f16x2(w00, w01);
                bfr[1] = pack_f16x2(w08, w09);
                mma16816(acc[0][nt], a0, bfr);
                mma16816(acc[1][nt], a1, bfr);
            }
        }
        __syncthreads();
        if (tid == 0 && it + 2 < NITER) issue(it + 2, b);
    }

    // ---- epilogue: out = scale*acc + scale*offset*rowsum + bias ----
#pragma unroll
    for (int nt = 0; nt < 2; nt++) {
        const int n = n0 + nw * 16 + nt * 8 + tg * 2;
        const float s0 = scale[n], s1 = scale[n + 1];
        const float t0 = s0 * offs[n], t1 = s1 * offs[n + 1];
        const float b0 = bias[n], b1 = bias[n + 1];
#pragma unroll
        for (int mt = 0; mt < 2; mt++) {
            const int m = mw * 32 + mt * 16 + g;
            const float r0 = g_rowsum[m];
            const float r1 = g_rowsum[m + 8];
            float2 v0, v1;
            v0.x = fmaf(acc[mt][nt][0], s0, fmaf(t0, r0, b0));
            v0.y = fmaf(acc[mt][nt][1], s1, fmaf(t1, r0, b1));
            v1.x = fmaf(acc[mt][nt][2], s0, fmaf(t0, r1, b0));
            v1.y = fmaf(acc[mt][nt][3], s1, fmaf(t1, r1, b1));
            *reinterpret_cast<float2*>(out + (size_t)m * NW + n) = v0;
            *reinterpret_cast<float2*>(out + (size_t)(m + 8) * NW + n) = v1;
        }
    }
}

// ---------------- launch ----------------
typedef CUresult (*EncodeFn)(CUtensorMap*, CUtensorMapDataType, cuuint32_t, void*,
    const cuuint64_t*, const cuuint64_t*, const cuuint32_t*, const cuuint32_t*,
    CUtensorMapInterleave, CUtensorMapSwizzle, CUtensorMapL2promotion, CUtensorMapFloatOOBfill);

extern "C" void kernel_launch(void* const* d_in, const int* in_sizes, int n_in,
                              void* d_out, int out_size) {
    const float* x     = (const float*)d_in[0];
    void*        w     = (void*)d_in[1];
    const float* scale = (const float*)d_in[2];
    const float* offs  = (const float*)d_in[3];
    const float* bias  = (const float*)d_in[4];
    float* out = (float*)d_out;

    // Build the weight tensormap (host-side, graph-capture safe: no stream ops)
    void* sym = nullptr;
    cudaDriverEntryPointQueryResult qr;
#if CUDART_VERSION >= 12050
    cudaGetDriverEntryPointByVersion("cuTensorMapEncodeTiled", &sym, 12000, cudaEnableDefault, &qr);
#else
    cudaGetDriverEntryPoint("cuTensorMapEncodeTiled", &sym, cudaEnableDefault, &qr);
#endif
    EncodeFn enc = (EncodeFn)sym;

    CUtensorMap tmw;
    cuuint64_t dims[2]    = {(cuuint64_t)NW, (cuuint64_t)NK};
    cuuint64_t strides[1] = {(cuuint64_t)NW * 4};
    cuuint32_t box[2]     = {32u, 128u};
    cuuint32_t es[2]      = {1u, 1u};
    enc(&tmw, CU_TENSOR_MAP_DATA_TYPE_UINT32, 2, w, dims, strides, box, es,
        CU_TENSOR_MAP_INTERLEAVE_NONE, CU_TENSOR_MAP_SWIZZLE_128B,
        CU_TENSOR_MAP_L2_PROMOTION_L2_128B, CU_TENSOR_MAP_FLOAT_OOB_FILL_NONE);

    cudaFuncSetAttribute(wqmm_main, cudaFuncAttributeMaxDynamicSharedMemorySize, SMEM_TOTAL);

    prep_x<<<128, 256>>>(x);
    prep_rowsum<<<NM, 128>>>(x);
    wqmm_main<<<NBLK, THREADS, SMEM_TOTAL>>>(tmw, scale, offs, bias, out);
}